// round 1
// baseline (speedup 1.0000x reference)
#include <cuda_runtime.h>
#include <stdint.h>

// Haar DWT level-1 on x: (B=32, L=4096, F=512) fp32.
// out[b, p, f]        = (x[b,2p,f] + x[b,2p+1,f]) * inv_sqrt2   (p in [0,2048))
// out[b, 2048+p, f]   = (x[b,2p,f] - x[b,2p+1,f]) * inv_sqrt2
//
// Pure bandwidth kernel: float4 vectorized, fully coalesced.

#define B 32
#define L 4096
#define F 512
#define HALF_L (L / 2)
#define F4 (F / 4)                      // 128 float4 per row
#define TOTAL_T (B * HALF_L * F4)       // 8,388,608 threads

__constant__ float c_inv_sqrt2 = 0.70710678118654752440f;

__global__ __launch_bounds__(256) void haar_dwt_kernel(
    const float4* __restrict__ x, float4* __restrict__ out)
{
    int t = blockIdx.x * blockDim.x + threadIdx.x;
    if (t >= TOTAL_T) return;

    int f4 = t & (F4 - 1);              // 0..127
    int p  = (t >> 7) & (HALF_L - 1);   // 0..2047
    int b  = t >> 18;                   // 0..31

    // input: two adjacent rows 2p and 2p+1
    long in_base = (long)b * (L * F4) + (long)(2 * p) * F4 + f4;
    float4 x0 = x[in_base];
    float4 x1 = x[in_base + F4];

    const float s = c_inv_sqrt2;
    float4 ca, cd;
    ca.x = (x0.x + x1.x) * s;  cd.x = (x0.x - x1.x) * s;
    ca.y = (x0.y + x1.y) * s;  cd.y = (x0.y - x1.y) * s;
    ca.z = (x0.z + x1.z) * s;  cd.z = (x0.z - x1.z) * s;
    ca.w = (x0.w + x1.w) * s;  cd.w = (x0.w - x1.w) * s;

    long out_base = (long)b * (L * F4) + (long)p * F4 + f4;
    out[out_base] = ca;
    out[out_base + (long)HALF_L * F4] = cd;
}

extern "C" void kernel_launch(void* const* d_in, const int* in_sizes, int n_in,
                              void* d_out, int out_size)
{
    const float4* x = (const float4*)d_in[0];
    float4* out = (float4*)d_out;

    int threads = 256;
    int blocks = (TOTAL_T + threads - 1) / threads;  // 32768
    haar_dwt_kernel<<<blocks, threads>>>(x, out);
}